// round 7
// baseline (speedup 1.0000x reference)
#include <cuda_runtime.h>
#include <cuda_bf16.h>

// B=8, SEQ=4096, DIM=64.
// out = scale * rope(Q) @ (rope(K)^T @ rope(V))   (associativity; no softmax)
// scale = 1/sqrt(64) = 0.125

#define BATCH   8
#define SEQ     4096
#define DIM     64
#define NC1     128           // k1 chunks per batch
#define CHUNK1  (SEQ / NC1)   // 32 rows per k1 CTA (2 halves of 16)

__device__ float g_partials[NC1 * BATCH * DIM * DIM];  // 16 MB
__device__ float g_M[BATCH * DIM * DIM];               // 128 KB

typedef unsigned long long ull;

__device__ __forceinline__ ull pk2(float x) {
    ull r; asm("mov.b64 %0, {%1,%1};" : "=l"(r) : "f"(x)); return r;
}
__device__ __forceinline__ void fma2(ull& d, ull a, ull b) {
    asm("fma.rn.f32x2 %0, %1, %2, %0;" : "+l"(d) : "l"(a), "l"(b));
}
__device__ __forceinline__ float2 up2(ull v) {
    float2 r; asm("mov.b64 {%0,%1}, %2;" : "=f"(r.x), "=f"(r.y) : "l"(v)); return r;
}
__device__ __forceinline__ float4 rope4(float4 x, float4 f) {
    float4 o;
    o.x = x.x * f.x - x.y * f.y;  o.y = x.x * f.y + x.y * f.x;
    o.z = x.z * f.z - x.w * f.w;  o.w = x.z * f.w + x.w * f.z;
    return o;
}
// interleaved 16B-chunk slot: even chunks -> words 0..31, odd -> 32..63.
#define SLOT(c) ((((c) >> 1) + 8 * ((c) & 1)) * 4)

// ---------------------------------------------------------------------------
// Kernel 1: partial M = sum_rows rope(k) ⊗ rope(v).  128 threads, 32 rows.
// Half h = t>>6 handles 16 rows; thread = 8 rows x 8 cols of the 64x64 M.
// Halves combine through smem so each CTA writes ONE partial tile.
// ---------------------------------------------------------------------------
#define CPAD 68

__global__ __launch_bounds__(128) void kv_outer_kernel(
    const float* __restrict__ K, const float* __restrict__ V,
    const float* __restrict__ FK, const float* __restrict__ FV)
{
    const int b = blockIdx.y;
    const int c = blockIdx.x;
    const int t = threadIdx.x;

    __shared__ float sk[CHUNK1 * DIM];    // 8 KB plain
    __shared__ float svI[CHUNK1 * DIM];   // 8 KB interleaved
    __shared__ float comb[DIM * CPAD];    // 17 KB half-combine buffer

    const float4* K4  = (const float4*)(K  + ((size_t)b * SEQ + c * CHUNK1) * DIM);
    const float4* V4  = (const float4*)(V  + ((size_t)b * SEQ + c * CHUNK1) * DIM);
    const float4* FK4 = (const float4*)(FK + (size_t)c * CHUNK1 * DIM);
    const float4* FV4 = (const float4*)(FV + (size_t)c * CHUNK1 * DIM);

    // stage + rope 32x64 tiles: 512 float4 each, 4 per thread
#pragma unroll
    for (int u = 0; u < 4; u++) {
        const int f  = t + 128 * u;
        const int r  = f >> 4;
        const int c4 = f & 15;
        *(float4*)&sk[r * DIM + 4 * c4]     = rope4(K4[f], FK4[f]);
        *(float4*)&svI[r * DIM + SLOT(c4)]  = rope4(V4[f], FV4[f]);
    }
    __syncthreads();

    const int h  = t >> 6;
    const int lt = t & 63;
    const int ti = lt >> 3;      // rows 8ti..8ti+7
    const int tj = lt & 7;       // cols 8tj..8tj+7
    const int i0 = 8 * ti;
    const int j0 = 8 * tj;

    ull acc[8][4];
#pragma unroll
    for (int i = 0; i < 8; i++)
#pragma unroll
        for (int p = 0; p < 4; p++) acc[i][p] = 0ULL;

    const int rbase = 16 * h;
#pragma unroll
    for (int r = 0; r < 16; r++) {
        const int row = rbase + r;
        const float4 ka = *(const float4*)&sk[row * DIM + i0];
        const float4 kb = *(const float4*)&sk[row * DIM + i0 + 4];
        const ull* vA = (const ull*)&svI[row * DIM + 4 * tj];
        const ull* vB = (const ull*)&svI[row * DIM + 32 + 4 * tj];
        const ull v0 = vA[0], v1 = vA[1], v2 = vB[0], v3 = vB[1];
        const ull k0 = pk2(ka.x), k1 = pk2(ka.y), k2 = pk2(ka.z), k3 = pk2(ka.w);
        const ull k4 = pk2(kb.x), k5 = pk2(kb.y), k6 = pk2(kb.z), k7 = pk2(kb.w);
        fma2(acc[0][0], k0, v0); fma2(acc[0][1], k0, v1); fma2(acc[0][2], k0, v2); fma2(acc[0][3], k0, v3);
        fma2(acc[1][0], k1, v0); fma2(acc[1][1], k1, v1); fma2(acc[1][2], k1, v2); fma2(acc[1][3], k1, v3);
        fma2(acc[2][0], k2, v0); fma2(acc[2][1], k2, v1); fma2(acc[2][2], k2, v2); fma2(acc[2][3], k2, v3);
        fma2(acc[3][0], k3, v0); fma2(acc[3][1], k3, v1); fma2(acc[3][2], k3, v2); fma2(acc[3][3], k3, v3);
        fma2(acc[4][0], k4, v0); fma2(acc[4][1], k4, v1); fma2(acc[4][2], k4, v2); fma2(acc[4][3], k4, v3);
        fma2(acc[5][0], k5, v0); fma2(acc[5][1], k5, v1); fma2(acc[5][2], k5, v2); fma2(acc[5][3], k5, v3);
        fma2(acc[6][0], k6, v0); fma2(acc[6][1], k6, v1); fma2(acc[6][2], k6, v2); fma2(acc[6][3], k6, v3);
        fma2(acc[7][0], k7, v0); fma2(acc[7][1], k7, v1); fma2(acc[7][2], k7, v2); fma2(acc[7][3], k7, v3);
    }

    // half 1 deposits, half 0 adds and writes the single partial tile
    if (h == 1) {
#pragma unroll
        for (int i = 0; i < 8; i++) {
            const float2 a0 = up2(acc[i][0]), a1 = up2(acc[i][1]);
            const float2 a2 = up2(acc[i][2]), a3 = up2(acc[i][3]);
            *(float4*)&comb[(i0 + i) * CPAD + j0] =
                make_float4(a0.x, a0.y, a1.x, a1.y);
            *(float4*)&comb[(i0 + i) * CPAD + j0 + 4] =
                make_float4(a2.x, a2.y, a3.x, a3.y);
        }
    }
    __syncthreads();
    if (h == 0) {
        float* P = &g_partials[((size_t)c * BATCH + b) * (DIM * DIM)];
#pragma unroll
        for (int i = 0; i < 8; i++) {
            const float4 c0 = *(const float4*)&comb[(i0 + i) * CPAD + j0];
            const float4 c1 = *(const float4*)&comb[(i0 + i) * CPAD + j0 + 4];
            const float2 a0 = up2(acc[i][0]), a1 = up2(acc[i][1]);
            const float2 a2 = up2(acc[i][2]), a3 = up2(acc[i][3]);
            *(float4*)&P[(i0 + i) * DIM + j0] =
                make_float4(a0.x + c0.x, a0.y + c0.y, a1.x + c0.z, a1.y + c0.w);
            *(float4*)&P[(i0 + i) * DIM + j0 + 4] =
                make_float4(a2.x + c1.x, a2.y + c1.y, a3.x + c1.z, a3.y + c1.w);
        }
    }
}

// ---------------------------------------------------------------------------
// Kernel 2: reduce NC1 partials -> g_M.  128 blocks x 64 threads,
// one float4 output per thread (8192 total), 128 chunk loads each.
// ---------------------------------------------------------------------------
__global__ __launch_bounds__(64) void reduce_kernel()
{
    const int idx = blockIdx.x * 64 + threadIdx.x;   // 0..8191 (float4)
    const float4* P = (const float4*)g_partials;
    float4 s0 = make_float4(0.f, 0.f, 0.f, 0.f);
    float4 s1 = make_float4(0.f, 0.f, 0.f, 0.f);
    float4 s2 = make_float4(0.f, 0.f, 0.f, 0.f);
    float4 s3 = make_float4(0.f, 0.f, 0.f, 0.f);
#pragma unroll 8
    for (int c = 0; c < NC1; c += 4) {
        const float4 a = P[(size_t)(c + 0) * 8192 + idx];
        const float4 b = P[(size_t)(c + 1) * 8192 + idx];
        const float4 d = P[(size_t)(c + 2) * 8192 + idx];
        const float4 e = P[(size_t)(c + 3) * 8192 + idx];
        s0.x += a.x; s0.y += a.y; s0.z += a.z; s0.w += a.w;
        s1.x += b.x; s1.y += b.y; s1.z += b.z; s1.w += b.w;
        s2.x += d.x; s2.y += d.y; s2.z += d.z; s2.w += d.w;
        s3.x += e.x; s3.y += e.y; s3.z += e.z; s3.w += e.w;
    }
    ((float4*)g_M)[idx] = make_float4(s0.x + s1.x + s2.x + s3.x,
                                      s0.y + s1.y + s2.y + s3.y,
                                      s0.z + s1.z + s2.z + s3.z,
                                      s0.w + s1.w + s2.w + s3.w);
}

// ---------------------------------------------------------------------------
// Kernel 3: out = scale * rope(Q) @ M[b].  128 threads, 32 q-rows per CTA.
// Thread = 2 rows x 8 cols. q transposed (pad 34); M interleaved.
// ---------------------------------------------------------------------------
#define QPAD 34

__global__ __launch_bounds__(128) void qm_kernel(
    const float* __restrict__ Q, const float* __restrict__ FQ,
    float* __restrict__ OUT)
{
    const int b  = blockIdx.y;
    const int rc = blockIdx.x;   // 32-row chunk, 0..127
    const int t  = threadIdx.x;

    __shared__ float sMI[DIM * DIM];       // 16 KB interleaved
    __shared__ float sqT[DIM * QPAD];      // 8.5 KB [d][row], pad 34 (even)

    // stage M[b] interleaved: 1024 float4, 8 per thread
    {
        const float4* Ms = (const float4*)&g_M[(size_t)b * DIM * DIM];
#pragma unroll
        for (int u = 0; u < 8; u++) {
            const int f  = t + 128 * u;
            const int d  = f >> 4;
            const int c4 = f & 15;
            *(float4*)&sMI[d * DIM + SLOT(c4)] = Ms[f];
        }
    }

    // stage rope(Q) transposed: 512 float4, 4 per thread
    const size_t gbase = ((size_t)b * SEQ + (size_t)rc * CHUNK1) * DIM;
    {
        const float4* Q4 = (const float4*)(Q + gbase);
        const float4* F4 = (const float4*)(FQ + (size_t)rc * CHUNK1 * DIM);
#pragma unroll
        for (int u = 0; u < 4; u++) {
            const int f   = t + 128 * u;
            const int row = f >> 4;          // 0..31
            const int d0  = 4 * (f & 15);
            const float4 o = rope4(Q4[f], F4[f]);
            sqT[(d0 + 0) * QPAD + row] = o.x;
            sqT[(d0 + 1) * QPAD + row] = o.y;
            sqT[(d0 + 2) * QPAD + row] = o.z;
            sqT[(d0 + 3) * QPAD + row] = o.w;
        }
    }
    __syncthreads();

    const int ti = t >> 3;    // 0..15 -> rows 2ti, 2ti+1
    const int tj = t & 7;     // cols 8tj..8tj+7
    const int i0 = 2 * ti;
    const int j0 = 8 * tj;

    ull acc[2][4];
#pragma unroll
    for (int i = 0; i < 2; i++)
#pragma unroll
        for (int p = 0; p < 4; p++) acc[i][p] = 0ULL;

#pragma unroll 16
    for (int d = 0; d < DIM; d++) {
        const float2 qq = *(const float2*)&sqT[d * QPAD + i0];
        const ull* mA = (const ull*)&sMI[d * DIM + 4 * tj];
        const ull* mB = (const ull*)&sMI[d * DIM + 32 + 4 * tj];
        const ull m0 = mA[0], m1 = mA[1], m2 = mB[0], m3 = mB[1];
        const ull q0 = pk2(qq.x), q1 = pk2(qq.y);
        fma2(acc[0][0], q0, m0); fma2(acc[0][1], q0, m1);
        fma2(acc[0][2], q0, m2); fma2(acc[0][3], q0, m3);
        fma2(acc[1][0], q1, m0); fma2(acc[1][1], q1, m1);
        fma2(acc[1][2], q1, m2); fma2(acc[1][3], q1, m3);
    }

    const float scale = 0.125f;   // 1/sqrt(64)
    float* O = OUT + gbase;
#pragma unroll
    for (int i = 0; i < 2; i++) {
        const float2 a0 = up2(acc[i][0]), a1 = up2(acc[i][1]);
        const float2 a2 = up2(acc[i][2]), a3 = up2(acc[i][3]);
        *(float4*)&O[(size_t)(i0 + i) * DIM + j0] =
            make_float4(a0.x * scale, a0.y * scale, a1.x * scale, a1.y * scale);
        *(float4*)&O[(size_t)(i0 + i) * DIM + j0 + 4] =
            make_float4(a2.x * scale, a2.y * scale, a3.x * scale, a3.y * scale);
    }
}

// ---------------------------------------------------------------------------
extern "C" void kernel_launch(void* const* d_in, const int* in_sizes, int n_in,
                              void* d_out, int out_size)
{
    const float* q  = (const float*)d_in[0];
    const float* k  = (const float*)d_in[1];
    const float* v  = (const float*)d_in[2];
    const float* fq = (const float*)d_in[3];
    const float* fk = (const float*)d_in[4];
    const float* fv = (const float*)d_in[5];
    float* out = (float*)d_out;

    kv_outer_kernel<<<dim3(NC1, BATCH), 128>>>(k, v, fk, fv);
    reduce_kernel<<<128, 64>>>();
    qm_kernel<<<dim3(NC1, BATCH), 128>>>(q, fq, out);
}